// round 5
// baseline (speedup 1.0000x reference)
#include <cuda_runtime.h>
#include <cuda_bf16.h>

// ---------------------------------------------------------------------------
// RGBLambertianRendererWithVisibility — R5
//   Two launches per call: [detect_idx, shade_fused].
//   shade_fused = R3 half-warp/LDG.128 shade + last-block finalize that also
//   re-zeros the accumulator and done-counter (clean state per call;
//   __device__ globals are zero at module load, covering call 1).
// ---------------------------------------------------------------------------

#define MAX_RAYS 65536
__device__ float        g_acc[MAX_RAYS * 4];   // zero-initialized at load
__device__ int          g_idx_is64;
__device__ unsigned int g_done;                // zero-initialized at load

// Single-block dtype detection (int32 vs int64 ray_indices). Inspect the last
// 2048 of the first N int32 words (in-bounds for both layouts): sorted
// indices there are large/nonzero for int32; int64 interleaves zero words.
__global__ void detect_idx_kernel(const int* __restrict__ words, int n_words_safe) {
    int end   = n_words_safe;
    int start = end - 2048; if (start < 0) start = 0;
    int z = 0;
    for (int i = start + threadIdx.x; i < end; i += blockDim.x)
        z |= (words[i] == 0);
    int any = __syncthreads_or(z);
    if (threadIdx.x == 0) g_idx_is64 = any ? 1 : 0;
}

// --- fused shade + scatter + (last block) finalize, L == 64 -----------------
__global__ __launch_bounds__(256) void shade_fused_kernel(
        const float* __restrict__ albedos,
        const float* __restrict__ normals,
        const float* __restrict__ ldir,
        const float* __restrict__ lcol,
        const float* __restrict__ vis,
        const float* __restrict__ weights,
        const void*  __restrict__ ray_idx,
        const float* __restrict__ bg,
        float*       __restrict__ out,
        int N, int R, unsigned int nblocks) {
    int tid  = threadIdx.x;
    int warp = tid >> 5;
    int lane = tid & 31;
    int half = lane >> 4;
    int sub  = lane & 15;
    int s    = blockIdx.x * 16 + warp * 2 + half;   // sample id
    int sc   = (s < N) ? s : (N - 1);               // clamped for loads
    bool live = (s < N);

    const float4* ldp = (const float4*)(ldir + (size_t)sc * 192);
    const float4* lcp = (const float4*)(lcol + (size_t)sc * 192);
    const float4* vp  = (const float4*)(vis  + (size_t)sc * 64);

    // 7 independent LDG.128
    float4 d0 = ldp[sub * 3 + 0];
    float4 d1 = ldp[sub * 3 + 1];
    float4 d2 = ldp[sub * 3 + 2];
    float4 c0 = lcp[sub * 3 + 0];
    float4 c1 = lcp[sub * 3 + 1];
    float4 c2 = lcp[sub * 3 + 2];
    float4 v  = vp[sub];

    float nx = normals[sc * 3 + 0];
    float ny = normals[sc * 3 + 1];
    float nz = normals[sc * 3 + 2];

    float t0 = fmaf(nx, d0.x, fmaf(ny, d0.y, nz * d0.z));
    float t1 = fmaf(nx, d0.w, fmaf(ny, d1.x, nz * d1.y));
    float t2 = fmaf(nx, d1.z, fmaf(ny, d1.w, nz * d2.x));
    float t3 = fmaf(nx, d2.y, fmaf(ny, d2.z, nz * d2.w));

    int cnt = (t0 > 0.f) + (t1 > 0.f) + (t2 > 0.f) + (t3 > 0.f);

    t0 = fminf(fmaxf(t0, 0.f), 1.f) * v.x;
    t1 = fminf(fmaxf(t1, 0.f), 1.f) * v.y;
    t2 = fminf(fmaxf(t2, 0.f), 1.f) * v.z;
    t3 = fminf(fmaxf(t3, 0.f), 1.f) * v.w;

    float s0 = fmaf(t0, c0.x, fmaf(t1, c0.w, fmaf(t2, c1.z, t3 * c2.y)));
    float s1 = fmaf(t0, c0.y, fmaf(t1, c1.x, fmaf(t2, c1.w, t3 * c2.z)));
    float s2 = fmaf(t0, c0.z, fmaf(t1, c1.y, fmaf(t2, c2.x, t3 * c2.w)));

    #pragma unroll
    for (int off = 8; off; off >>= 1) {
        s0  += __shfl_xor_sync(0xFFFFFFFFu, s0,  off);
        s1  += __shfl_xor_sync(0xFFFFFFFFu, s1,  off);
        s2  += __shfl_xor_sync(0xFFFFFFFFu, s2,  off);
        cnt += __shfl_xor_sync(0xFFFFFFFFu, cnt, off);
    }

    if (sub == 0) {
        float c   = (cnt > 0) ? (float)cnt : 1.0f;
        float inv = 1.0f / c;
        float w   = live ? weights[sc] : 0.0f;     // dead sample contributes 0
        int r;
        if (g_idx_is64) r = (int)((const long long*)ray_idx)[sc];
        else            r = ((const int*)ray_idx)[sc];
        float a0 = albedos[sc * 3 + 0];
        float a1 = albedos[sc * 3 + 1];
        float a2 = albedos[sc * 3 + 2];
        atomicAdd(&g_acc[r * 4 + 0], w * a0 * s0 * inv);
        atomicAdd(&g_acc[r * 4 + 1], w * a1 * s1 * inv);
        atomicAdd(&g_acc[r * 4 + 2], w * a2 * s2 * inv);
        atomicAdd(&g_acc[r * 4 + 3], w);
    }

    // ---- last-block finalize ---------------------------------------------
    __threadfence();
    __shared__ int is_last;
    if (tid == 0) is_last = (atomicAdd(&g_done, 1u) == nblocks - 1u) ? 1 : 0;
    __syncthreads();
    if (is_last) {
        for (int r = tid; r < R; r += blockDim.x) {
            float aw = __ldcg(&g_acc[r * 4 + 3]);
            float x0 = __ldcg(&g_acc[r * 4 + 0]);
            float x1 = __ldcg(&g_acc[r * 4 + 1]);
            float x2 = __ldcg(&g_acc[r * 4 + 2]);
            float one_m = 1.0f - aw;
            float xr[3] = { x0 + bg[r * 3 + 0] * one_m,
                            x1 + bg[r * 3 + 1] * one_m,
                            x2 + bg[r * 3 + 2] * one_m };
            #pragma unroll
            for (int c = 0; c < 3; ++c) {
                float x = xr[c];
                float safe = fmaxf(x, 1e-8f);
                float y = (x <= 0.0031308f)
                        ? (12.92f * x)
                        : (1.055f * powf(safe, 1.0f / 2.4f) - 0.055f);
                out[r * 3 + c] = y;
            }
            // re-zero for the next call (graph replay)
            g_acc[r * 4 + 0] = 0.0f;
            g_acc[r * 4 + 1] = 0.0f;
            g_acc[r * 4 + 2] = 0.0f;
            g_acc[r * 4 + 3] = 0.0f;
        }
        __threadfence();
        __syncthreads();
        if (tid == 0) g_done = 0;   // reset counter for next call
    }
}

// --- generic path (L != 64): zero + shade + finalize, unfused ---------------
__global__ void zero_acc_kernel(int n4) {
    int i = blockIdx.x * blockDim.x + threadIdx.x;
    if (i < n4) g_acc[i] = 0.0f;
}

__global__ void shade_kernel_generic(
        const float* __restrict__ albedos,
        const float* __restrict__ normals,
        const float* __restrict__ ldir,
        const float* __restrict__ lcol,
        const float* __restrict__ vis,
        const float* __restrict__ weights,
        const void*  __restrict__ ray_idx,
        int N, int L) {
    int gwarp = (blockIdx.x * blockDim.x + threadIdx.x) >> 5;
    int lane  = threadIdx.x & 31;
    if (gwarp >= N) return;
    float nx = normals[gwarp * 3 + 0];
    float ny = normals[gwarp * 3 + 1];
    float nz = normals[gwarp * 3 + 2];
    const float* ldp = ldir + (size_t)gwarp * L * 3;
    const float* lcp = lcol + (size_t)gwarp * L * 3;
    const float* vp  = vis  + (size_t)gwarp * L;
    float s0 = 0.f, s1 = 0.f, s2 = 0.f;
    int cnt = 0;
    for (int j = lane; j < L; j += 32) {
        float dx = ldp[j * 3 + 0], dy = ldp[j * 3 + 1], dz = ldp[j * 3 + 2];
        float d  = fmaf(nx, dx, fmaf(ny, dy, nz * dz));
        cnt += (d > 0.f) ? 1 : 0;
        d = fminf(fmaxf(d, 0.f), 1.f);
        float dv = d * vp[j];
        s0 = fmaf(dv, lcp[j * 3 + 0], s0);
        s1 = fmaf(dv, lcp[j * 3 + 1], s1);
        s2 = fmaf(dv, lcp[j * 3 + 2], s2);
    }
    #pragma unroll
    for (int off = 16; off; off >>= 1) {
        s0  += __shfl_xor_sync(0xFFFFFFFFu, s0,  off);
        s1  += __shfl_xor_sync(0xFFFFFFFFu, s1,  off);
        s2  += __shfl_xor_sync(0xFFFFFFFFu, s2,  off);
        cnt += __shfl_xor_sync(0xFFFFFFFFu, cnt, off);
    }
    if (lane == 0) {
        float c   = (cnt > 0) ? (float)cnt : 1.0f;
        float inv = 1.0f / c;
        float w   = weights[gwarp];
        int r;
        if (g_idx_is64) r = (int)((const long long*)ray_idx)[gwarp];
        else            r = ((const int*)ray_idx)[gwarp];
        atomicAdd(&g_acc[r * 4 + 0], w * albedos[gwarp * 3 + 0] * s0 * inv);
        atomicAdd(&g_acc[r * 4 + 1], w * albedos[gwarp * 3 + 1] * s1 * inv);
        atomicAdd(&g_acc[r * 4 + 2], w * albedos[gwarp * 3 + 2] * s2 * inv);
        atomicAdd(&g_acc[r * 4 + 3], w);
    }
}

__global__ void finalize_kernel(const float* __restrict__ bg,
                                float* __restrict__ out, int R) {
    int r = blockIdx.x * blockDim.x + threadIdx.x;
    if (r >= R) return;
    float aw = g_acc[r * 4 + 3];
    float one_m = 1.0f - aw;
    #pragma unroll
    for (int c = 0; c < 3; ++c) {
        float x = g_acc[r * 4 + c] + bg[r * 3 + c] * one_m;
        float safe = fmaxf(x, 1e-8f);
        float y = (x <= 0.0031308f) ? (12.92f * x)
                                    : (1.055f * powf(safe, 1.0f / 2.4f) - 0.055f);
        out[r * 3 + c] = y;
    }
}

extern "C" void kernel_launch(void* const* d_in, const int* in_sizes, int n_in,
                              void* d_out, int out_size) {
    const float* albedos = (const float*)d_in[0];
    const float* normals = (const float*)d_in[1];
    const float* ldir    = (const float*)d_in[2];
    const float* lcol    = (const float*)d_in[3];
    const float* vis     = (const float*)d_in[4];
    const float* bg      = (const float*)d_in[5];
    const float* weights = (const float*)d_in[6];
    const void*  ray_idx = (const void*) d_in[7];
    float* out = (float*)d_out;

    int N = in_sizes[0] / 3;
    int L = (N > 0) ? in_sizes[2] / (N * 3) : 1;
    int R = out_size / 3;
    if (R > MAX_RAYS) R = MAX_RAYS;

    // 1) dtype detection (single block, self-contained)
    detect_idx_kernel<<<1, 1024>>>((const int*)ray_idx, in_sizes[7]);

    if (L == 64) {
        // 2) fused shade + scatter + last-block finalize (16 samples/block)
        unsigned int blocks = (unsigned int)((N + 15) / 16);
        shade_fused_kernel<<<blocks, 256>>>(
            albedos, normals, ldir, lcol, vis, weights, ray_idx,
            bg, out, N, R, blocks);
    } else {
        int n4 = R * 4;
        zero_acc_kernel<<<(n4 + 255) / 256, 256>>>(n4);
        int blocks = (N + 7) / 8;
        shade_kernel_generic<<<blocks, 256>>>(
            albedos, normals, ldir, lcol, vis, weights, ray_idx, N, L);
        finalize_kernel<<<(R + 255) / 256, 256>>>(bg, out, R);
    }
}

// round 6
// speedup vs baseline: 1.4654x; 1.4654x over previous
#include <cuda_runtime.h>
#include <cuda_bf16.h>
#include <cstdint>

// ---------------------------------------------------------------------------
// RGBLambertianRendererWithVisibility — R6
//   TMA bulk-copy (cp.async.bulk 1D, UBLKCP) of each block's light data into
//   smem — bypasses the per-SM L1TEX MSHR cap that limited LDG to ~2.6-3.7TB/s.
//   Compute = R4's conflict-free half-warp-per-sample smem math.
//   Launches: detect, zero, shade_tma, finalize (no fences in hot path).
// ---------------------------------------------------------------------------

#define MAX_RAYS 65536
#define SPB 16   // samples per block

__device__ float g_acc[MAX_RAYS * 4];
__device__ int   g_idx_is64;

__global__ void zero_acc_kernel(int n4) {
    int i = blockIdx.x * blockDim.x + threadIdx.x;
    if (i < n4) g_acc[i] = 0.0f;
}

// Single-block dtype detection (int32 vs int64 ray_indices): look at the last
// 2048 of the first N int32 words (in-bounds either way). Sorted nonneg
// indices are nonzero there for int32; int64 interleaves zero high words.
__global__ void detect_idx_kernel(const int* __restrict__ words, int n_words_safe) {
    int end   = n_words_safe;
    int start = end - 2048; if (start < 0) start = 0;
    int z = 0;
    for (int i = start + threadIdx.x; i < end; i += blockDim.x)
        z |= (words[i] == 0);
    int any = __syncthreads_or(z);
    if (threadIdx.x == 0) g_idx_is64 = any ? 1 : 0;
}

__device__ __forceinline__ uint32_t smem_u32(const void* p) {
    uint32_t a;
    asm("{ .reg .u64 t; cvta.to.shared.u64 t, %1; cvt.u32.u64 %0, t; }"
        : "=r"(a) : "l"(p));
    return a;
}

// --- main fused pass: 256 threads, 16 samples/block, TMA-staged smem --------
__global__ __launch_bounds__(256) void shade_tma_kernel(
        const float* __restrict__ albedos,
        const float* __restrict__ normals,
        const float* __restrict__ ldir,
        const float* __restrict__ lcol,
        const float* __restrict__ vis,
        const float* __restrict__ weights,
        const void*  __restrict__ ray_idx,
        int N) {
    __shared__ __align__(16) float sm_dir[SPB * 192];   // 12 KB
    __shared__ __align__(16) float sm_col[SPB * 192];   // 12 KB
    __shared__ __align__(16) float sm_vis[SPB * 64];    //  4 KB
    __shared__ __align__(8)  unsigned long long sm_mbar;

    int tid  = threadIdx.x;
    int base = blockIdx.x * SPB;
    int nloc = N - base; if (nloc > SPB) nloc = SPB;

    uint32_t mbar = smem_u32(&sm_mbar);

    if (tid == 0) {
        asm volatile("mbarrier.init.shared.b64 [%0], 1;" :: "r"(mbar) : "memory");
    }
    __syncthreads();

    if (tid == 0) {
        unsigned db = (unsigned)nloc * 768u;   // dir bytes
        unsigned vb = (unsigned)nloc * 256u;   // vis bytes
        unsigned total = db * 2u + vb;
        asm volatile("mbarrier.arrive.expect_tx.shared.b64 _, [%0], %1;"
                     :: "r"(mbar), "r"(total) : "memory");
        asm volatile(
            "cp.async.bulk.shared::cta.global.mbarrier::complete_tx::bytes [%0], [%1], %2, [%3];"
            :: "r"(smem_u32(sm_dir)), "l"(ldir + (size_t)base * 192),
               "r"(db), "r"(mbar) : "memory");
        asm volatile(
            "cp.async.bulk.shared::cta.global.mbarrier::complete_tx::bytes [%0], [%1], %2, [%3];"
            :: "r"(smem_u32(sm_col)), "l"(lcol + (size_t)base * 192),
               "r"(db), "r"(mbar) : "memory");
        asm volatile(
            "cp.async.bulk.shared::cta.global.mbarrier::complete_tx::bytes [%0], [%1], %2, [%3];"
            :: "r"(smem_u32(sm_vis)), "l"(vis + (size_t)base * 64),
               "r"(vb), "r"(mbar) : "memory");
    }

    // all threads wait on the barrier (phase 0; HW-sleep try_wait loop)
    {
        uint32_t done;
        asm volatile(
            "{\n\t"
            ".reg .pred p;\n\t"
            "mbarrier.try_wait.parity.acquire.cta.shared::cta.b64 p, [%1], 0;\n\t"
            "selp.b32 %0, 1, 0, p;\n\t"
            "}" : "=r"(done) : "r"(mbar) : "memory");
        if (!done) {
            asm volatile(
                "{\n\t"
                ".reg .pred P1;\n\t"
                "WAIT_LOOP_%=:\n\t"
                "mbarrier.try_wait.parity.acquire.cta.shared::cta.b64 P1, [%0], 0, 0x989680;\n\t"
                "@P1 bra.uni WAIT_DONE_%=;\n\t"
                "bra.uni WAIT_LOOP_%=;\n\t"
                "WAIT_DONE_%=:\n\t"
                "}" :: "r"(mbar) : "memory");
        }
    }

    // ---- compute: half-warp per sample -------------------------------------
    int warp = tid >> 5;
    int lane = tid & 31;
    int half = lane >> 4;
    int sub  = lane & 15;
    int sl   = warp * 2 + half;        // local sample 0..15
    int s    = base + sl;
    bool live = (s < N);
    int sll  = live ? sl : 0;          // clamp smem reads to valid data

    const float4* sd = (const float4*)(sm_dir + sll * 192);
    const float4* sc = (const float4*)(sm_col + sll * 192);
    const float4* sv = (const float4*)(sm_vis + sll * 64);

    float4 d0 = sd[sub * 3 + 0];
    float4 d1 = sd[sub * 3 + 1];
    float4 d2 = sd[sub * 3 + 2];
    float4 c0 = sc[sub * 3 + 0];
    float4 c1 = sc[sub * 3 + 1];
    float4 c2 = sc[sub * 3 + 2];
    float4 v  = sv[sub];

    int scl = live ? s : 0;
    float nx = normals[scl * 3 + 0];
    float ny = normals[scl * 3 + 1];
    float nz = normals[scl * 3 + 2];

    float t0 = fmaf(nx, d0.x, fmaf(ny, d0.y, nz * d0.z));
    float t1 = fmaf(nx, d0.w, fmaf(ny, d1.x, nz * d1.y));
    float t2 = fmaf(nx, d1.z, fmaf(ny, d1.w, nz * d2.x));
    float t3 = fmaf(nx, d2.y, fmaf(ny, d2.z, nz * d2.w));

    int cnt = (t0 > 0.f) + (t1 > 0.f) + (t2 > 0.f) + (t3 > 0.f);

    t0 = fminf(fmaxf(t0, 0.f), 1.f) * v.x;
    t1 = fminf(fmaxf(t1, 0.f), 1.f) * v.y;
    t2 = fminf(fmaxf(t2, 0.f), 1.f) * v.z;
    t3 = fminf(fmaxf(t3, 0.f), 1.f) * v.w;

    float s0 = fmaf(t0, c0.x, fmaf(t1, c0.w, fmaf(t2, c1.z, t3 * c2.y)));
    float s1 = fmaf(t0, c0.y, fmaf(t1, c1.x, fmaf(t2, c1.w, t3 * c2.z)));
    float s2 = fmaf(t0, c0.z, fmaf(t1, c1.y, fmaf(t2, c2.x, t3 * c2.w)));

    #pragma unroll
    for (int off = 8; off; off >>= 1) {
        s0  += __shfl_xor_sync(0xFFFFFFFFu, s0,  off);
        s1  += __shfl_xor_sync(0xFFFFFFFFu, s1,  off);
        s2  += __shfl_xor_sync(0xFFFFFFFFu, s2,  off);
        cnt += __shfl_xor_sync(0xFFFFFFFFu, cnt, off);
    }

    if (sub == 0 && live) {
        float c   = (cnt > 0) ? (float)cnt : 1.0f;
        float inv = 1.0f / c;
        float w   = weights[s];
        int r;
        if (g_idx_is64) r = (int)((const long long*)ray_idx)[s];
        else            r = ((const int*)ray_idx)[s];
        float a0 = albedos[s * 3 + 0];
        float a1 = albedos[s * 3 + 1];
        float a2 = albedos[s * 3 + 2];
        atomicAdd(&g_acc[r * 4 + 0], w * a0 * s0 * inv);
        atomicAdd(&g_acc[r * 4 + 1], w * a1 * s1 * inv);
        atomicAdd(&g_acc[r * 4 + 2], w * a2 * s2 * inv);
        atomicAdd(&g_acc[r * 4 + 3], w);
    }
}

__global__ void finalize_kernel(const float* __restrict__ bg,
                                float* __restrict__ out, int R) {
    int r = blockIdx.x * blockDim.x + threadIdx.x;
    if (r >= R) return;
    float aw = g_acc[r * 4 + 3];
    float one_m = 1.0f - aw;
    #pragma unroll
    for (int c = 0; c < 3; ++c) {
        float x = g_acc[r * 4 + c] + bg[r * 3 + c] * one_m;
        float safe = fmaxf(x, 1e-8f);
        float y = (x <= 0.0031308f) ? (12.92f * x)
                                    : (1.055f * powf(safe, 1.0f / 2.4f) - 0.055f);
        out[r * 3 + c] = y;
    }
}

// Fallback for L != 64
__global__ void shade_kernel_generic(
        const float* __restrict__ albedos,
        const float* __restrict__ normals,
        const float* __restrict__ ldir,
        const float* __restrict__ lcol,
        const float* __restrict__ vis,
        const float* __restrict__ weights,
        const void*  __restrict__ ray_idx,
        int N, int L) {
    int gwarp = (blockIdx.x * blockDim.x + threadIdx.x) >> 5;
    int lane  = threadIdx.x & 31;
    if (gwarp >= N) return;
    float nx = normals[gwarp * 3 + 0];
    float ny = normals[gwarp * 3 + 1];
    float nz = normals[gwarp * 3 + 2];
    const float* ldp = ldir + (size_t)gwarp * L * 3;
    const float* lcp = lcol + (size_t)gwarp * L * 3;
    const float* vp  = vis  + (size_t)gwarp * L;
    float s0 = 0.f, s1 = 0.f, s2 = 0.f;
    int cnt = 0;
    for (int j = lane; j < L; j += 32) {
        float dx = ldp[j * 3 + 0], dy = ldp[j * 3 + 1], dz = ldp[j * 3 + 2];
        float d  = fmaf(nx, dx, fmaf(ny, dy, nz * dz));
        cnt += (d > 0.f) ? 1 : 0;
        d = fminf(fmaxf(d, 0.f), 1.f);
        float dv = d * vp[j];
        s0 = fmaf(dv, lcp[j * 3 + 0], s0);
        s1 = fmaf(dv, lcp[j * 3 + 1], s1);
        s2 = fmaf(dv, lcp[j * 3 + 2], s2);
    }
    #pragma unroll
    for (int off = 16; off; off >>= 1) {
        s0  += __shfl_xor_sync(0xFFFFFFFFu, s0,  off);
        s1  += __shfl_xor_sync(0xFFFFFFFFu, s1,  off);
        s2  += __shfl_xor_sync(0xFFFFFFFFu, s2,  off);
        cnt += __shfl_xor_sync(0xFFFFFFFFu, cnt, off);
    }
    if (lane == 0) {
        float c   = (cnt > 0) ? (float)cnt : 1.0f;
        float inv = 1.0f / c;
        float w   = weights[gwarp];
        int r;
        if (g_idx_is64) r = (int)((const long long*)ray_idx)[gwarp];
        else            r = ((const int*)ray_idx)[gwarp];
        atomicAdd(&g_acc[r * 4 + 0], w * albedos[gwarp * 3 + 0] * s0 * inv);
        atomicAdd(&g_acc[r * 4 + 1], w * albedos[gwarp * 3 + 1] * s1 * inv);
        atomicAdd(&g_acc[r * 4 + 2], w * albedos[gwarp * 3 + 2] * s2 * inv);
        atomicAdd(&g_acc[r * 4 + 3], w);
    }
}

extern "C" void kernel_launch(void* const* d_in, const int* in_sizes, int n_in,
                              void* d_out, int out_size) {
    const float* albedos = (const float*)d_in[0];
    const float* normals = (const float*)d_in[1];
    const float* ldir    = (const float*)d_in[2];
    const float* lcol    = (const float*)d_in[3];
    const float* vis     = (const float*)d_in[4];
    const float* bg      = (const float*)d_in[5];
    const float* weights = (const float*)d_in[6];
    const void*  ray_idx = (const void*) d_in[7];
    float* out = (float*)d_out;

    int N = in_sizes[0] / 3;
    int L = (N > 0) ? in_sizes[2] / (N * 3) : 1;
    int R = out_size / 3;
    if (R > MAX_RAYS) R = MAX_RAYS;

    detect_idx_kernel<<<1, 1024>>>((const int*)ray_idx, in_sizes[7]);

    int n4 = R * 4;
    zero_acc_kernel<<<(n4 + 255) / 256, 256>>>(n4);

    if (L == 64) {
        int blocks = (N + SPB - 1) / SPB;
        shade_tma_kernel<<<blocks, 256>>>(
            albedos, normals, ldir, lcol, vis, weights, ray_idx, N);
    } else {
        int blocks = (N + 7) / 8;
        shade_kernel_generic<<<blocks, 256>>>(
            albedos, normals, ldir, lcol, vis, weights, ray_idx, N, L);
    }

    finalize_kernel<<<(R + 255) / 256, 256>>>(bg, out, R);
}

// round 7
// speedup vs baseline: 1.7733x; 1.2101x over previous
#include <cuda_runtime.h>
#include <cuda_bf16.h>
#include <cstdint>

// ---------------------------------------------------------------------------
// RGBLambertianRendererWithVisibility — R7
//   Persistent pipelined TMA kernel: 296 CTAs, 3-stage ring (84KB dynamic
//   smem), thread-0 producer keeps 3 bulk copies in flight; 256-thread
//   consumer runs half-warp-per-sample math per 16-sample tile.
// ---------------------------------------------------------------------------

#define MAX_RAYS 65536
#define SPB 16                         // samples per tile
#define NSTAGE 3
#define STAGE_FLOATS (SPB * 192 * 2 + SPB * 64)   // 7168 floats = 28672 B
#define SMEM_BYTES (NSTAGE * STAGE_FLOATS * 4)    // 86016 B

__device__ float g_acc[MAX_RAYS * 4];
__device__ int   g_idx_is64;

__global__ void zero_acc_kernel(int n4) {
    int i = blockIdx.x * blockDim.x + threadIdx.x;
    if (i < n4) g_acc[i] = 0.0f;
}

// int32 vs int64 ray_indices: inspect last 2048 of the first N int32 words
// (in-bounds for both layouts). Sorted nonneg indices are nonzero there for
// int32; int64 interleaves zero high words.
__global__ void detect_idx_kernel(const int* __restrict__ words, int n_words_safe) {
    int end   = n_words_safe;
    int start = end - 2048; if (start < 0) start = 0;
    int z = 0;
    for (int i = start + threadIdx.x; i < end; i += blockDim.x)
        z |= (words[i] == 0);
    int any = __syncthreads_or(z);
    if (threadIdx.x == 0) g_idx_is64 = any ? 1 : 0;
}

__device__ __forceinline__ uint32_t smem_u32(const void* p) {
    uint32_t a;
    asm("{ .reg .u64 t; cvta.to.shared.u64 t, %1; cvt.u32.u64 %0, t; }"
        : "=r"(a) : "l"(p));
    return a;
}

__device__ __forceinline__ void mbar_wait(uint32_t mbar, uint32_t parity) {
    uint32_t done;
    asm volatile(
        "{\n\t"
        ".reg .pred p;\n\t"
        "mbarrier.try_wait.parity.acquire.cta.shared::cta.b64 p, [%1], %2;\n\t"
        "selp.b32 %0, 1, 0, p;\n\t"
        "}" : "=r"(done) : "r"(mbar), "r"(parity) : "memory");
    if (!done) {
        asm volatile(
            "{\n\t"
            ".reg .pred P1;\n\t"
            "WAIT_LOOP_%=:\n\t"
            "mbarrier.try_wait.parity.acquire.cta.shared::cta.b64 P1, [%0], %1, 0x989680;\n\t"
            "@P1 bra.uni WAIT_DONE_%=;\n\t"
            "bra.uni WAIT_LOOP_%=;\n\t"
            "WAIT_DONE_%=:\n\t"
            "}" :: "r"(mbar), "r"(parity) : "memory");
    }
}

// issue the 3 bulk copies for one tile into one stage
__device__ __forceinline__ void issue_tile(
        float* stage_base, uint32_t mbar,
        const float* ldir, const float* lcol, const float* vis,
        int tile_base, int nloc) {
    unsigned db = (unsigned)nloc * 768u;
    unsigned vb = (unsigned)nloc * 256u;
    asm volatile("mbarrier.arrive.expect_tx.shared.b64 _, [%0], %1;"
                 :: "r"(mbar), "r"(db * 2u + vb) : "memory");
    asm volatile(
        "cp.async.bulk.shared::cta.global.mbarrier::complete_tx::bytes [%0], [%1], %2, [%3];"
        :: "r"(smem_u32(stage_base)), "l"(ldir + (size_t)tile_base * 192),
           "r"(db), "r"(mbar) : "memory");
    asm volatile(
        "cp.async.bulk.shared::cta.global.mbarrier::complete_tx::bytes [%0], [%1], %2, [%3];"
        :: "r"(smem_u32(stage_base + SPB * 192)), "l"(lcol + (size_t)tile_base * 192),
           "r"(db), "r"(mbar) : "memory");
    asm volatile(
        "cp.async.bulk.shared::cta.global.mbarrier::complete_tx::bytes [%0], [%1], %2, [%3];"
        :: "r"(smem_u32(stage_base + SPB * 384)), "l"(vis + (size_t)tile_base * 64),
           "r"(vb), "r"(mbar) : "memory");
}

// --- persistent pipelined shade (L == 64) -----------------------------------
__global__ __launch_bounds__(256) void shade_pipe_kernel(
        const float* __restrict__ albedos,
        const float* __restrict__ normals,
        const float* __restrict__ ldir,
        const float* __restrict__ lcol,
        const float* __restrict__ vis,
        const float* __restrict__ weights,
        const void*  __restrict__ ray_idx,
        int N, int ntiles) {
    extern __shared__ __align__(16) float smem[];
    __shared__ __align__(8) unsigned long long sm_mbar[NSTAGE];

    int tid = threadIdx.x;

    if (tid < NSTAGE) {
        uint32_t m = smem_u32(&sm_mbar[tid]);
        asm volatile("mbarrier.init.shared.b64 [%0], 1;" :: "r"(m) : "memory");
    }
    __syncthreads();

    // tiles owned by this block: t = blockIdx.x + j*gridDim.x
    int my_tiles = 0;
    {
        int first = blockIdx.x;
        if (first < ntiles) my_tiles = (ntiles - 1 - first) / gridDim.x + 1;
    }
    if (my_tiles == 0) return;

    // prologue: fill the pipe
    if (tid == 0) {
        int pre = my_tiles < NSTAGE ? my_tiles : NSTAGE;
        for (int d = 0; d < pre; ++d) {
            int t = blockIdx.x + d * gridDim.x;
            int tb = t * SPB;
            int nloc = N - tb; if (nloc > SPB) nloc = SPB;
            issue_tile(smem + d * STAGE_FLOATS, smem_u32(&sm_mbar[d]),
                       ldir, lcol, vis, tb, nloc);
        }
    }

    int warp = tid >> 5;
    int lane = tid & 31;
    int half = lane >> 4;
    int sub  = lane & 15;
    int sl   = warp * 2 + half;        // local sample 0..15

    int stage = 0, round = 0;          // parity = round & 1
    for (int j = 0; j < my_tiles; ++j) {
        int t    = blockIdx.x + j * gridDim.x;
        int base = t * SPB;

        mbar_wait(smem_u32(&sm_mbar[stage]), (uint32_t)(round & 1));

        float* stg = smem + stage * STAGE_FLOATS;
        int s    = base + sl;
        bool live = (s < N);
        int sll  = live ? sl : 0;

        const float4* sd = (const float4*)(stg + sll * 192);
        const float4* sc = (const float4*)(stg + SPB * 192 + sll * 192);
        const float4* sv = (const float4*)(stg + SPB * 384 + sll * 64);

        float4 d0 = sd[sub * 3 + 0];
        float4 d1 = sd[sub * 3 + 1];
        float4 d2 = sd[sub * 3 + 2];
        float4 c0 = sc[sub * 3 + 0];
        float4 c1 = sc[sub * 3 + 1];
        float4 c2 = sc[sub * 3 + 2];
        float4 v  = sv[sub];

        int scl = live ? s : 0;
        float nx = normals[scl * 3 + 0];
        float ny = normals[scl * 3 + 1];
        float nz = normals[scl * 3 + 2];

        float t0 = fmaf(nx, d0.x, fmaf(ny, d0.y, nz * d0.z));
        float t1 = fmaf(nx, d0.w, fmaf(ny, d1.x, nz * d1.y));
        float t2 = fmaf(nx, d1.z, fmaf(ny, d1.w, nz * d2.x));
        float t3 = fmaf(nx, d2.y, fmaf(ny, d2.z, nz * d2.w));

        int cnt = (t0 > 0.f) + (t1 > 0.f) + (t2 > 0.f) + (t3 > 0.f);

        t0 = fminf(fmaxf(t0, 0.f), 1.f) * v.x;
        t1 = fminf(fmaxf(t1, 0.f), 1.f) * v.y;
        t2 = fminf(fmaxf(t2, 0.f), 1.f) * v.z;
        t3 = fminf(fmaxf(t3, 0.f), 1.f) * v.w;

        float s0 = fmaf(t0, c0.x, fmaf(t1, c0.w, fmaf(t2, c1.z, t3 * c2.y)));
        float s1 = fmaf(t0, c0.y, fmaf(t1, c1.x, fmaf(t2, c1.w, t3 * c2.z)));
        float s2 = fmaf(t0, c0.z, fmaf(t1, c1.y, fmaf(t2, c2.x, t3 * c2.w)));

        #pragma unroll
        for (int off = 8; off; off >>= 1) {
            s0  += __shfl_xor_sync(0xFFFFFFFFu, s0,  off);
            s1  += __shfl_xor_sync(0xFFFFFFFFu, s1,  off);
            s2  += __shfl_xor_sync(0xFFFFFFFFu, s2,  off);
            cnt += __shfl_xor_sync(0xFFFFFFFFu, cnt, off);
        }

        if (sub == 0 && live) {
            float c   = (cnt > 0) ? (float)cnt : 1.0f;
            float inv = 1.0f / c;
            float w   = weights[s];
            int r;
            if (g_idx_is64) r = (int)((const long long*)ray_idx)[s];
            else            r = ((const int*)ray_idx)[s];
            float a0 = albedos[s * 3 + 0];
            float a1 = albedos[s * 3 + 1];
            float a2 = albedos[s * 3 + 2];
            atomicAdd(&g_acc[r * 4 + 0], w * a0 * s0 * inv);
            atomicAdd(&g_acc[r * 4 + 1], w * a1 * s1 * inv);
            atomicAdd(&g_acc[r * 4 + 2], w * a2 * s2 * inv);
            atomicAdd(&g_acc[r * 4 + 3], w);
        }

        __syncthreads();   // everyone done reading this stage

        // refill the stage with tile j+NSTAGE
        if (tid == 0) {
            int jn = j + NSTAGE;
            if (jn < my_tiles) {
                asm volatile("fence.proxy.async.shared::cta;" ::: "memory");
                int tn = blockIdx.x + jn * gridDim.x;
                int tb = tn * SPB;
                int nloc = N - tb; if (nloc > SPB) nloc = SPB;
                issue_tile(smem + stage * STAGE_FLOATS, smem_u32(&sm_mbar[stage]),
                           ldir, lcol, vis, tb, nloc);
            }
        }

        if (++stage == NSTAGE) { stage = 0; round ^= 1; }
    }
}

__global__ void finalize_kernel(const float* __restrict__ bg,
                                float* __restrict__ out, int R) {
    int r = blockIdx.x * blockDim.x + threadIdx.x;
    if (r >= R) return;
    float aw = g_acc[r * 4 + 3];
    float one_m = 1.0f - aw;
    #pragma unroll
    for (int c = 0; c < 3; ++c) {
        float x = g_acc[r * 4 + c] + bg[r * 3 + c] * one_m;
        float safe = fmaxf(x, 1e-8f);
        float y = (x <= 0.0031308f) ? (12.92f * x)
                                    : (1.055f * powf(safe, 1.0f / 2.4f) - 0.055f);
        out[r * 3 + c] = y;
    }
}

// Fallback for L != 64
__global__ void shade_kernel_generic(
        const float* __restrict__ albedos,
        const float* __restrict__ normals,
        const float* __restrict__ ldir,
        const float* __restrict__ lcol,
        const float* __restrict__ vis,
        const float* __restrict__ weights,
        const void*  __restrict__ ray_idx,
        int N, int L) {
    int gwarp = (blockIdx.x * blockDim.x + threadIdx.x) >> 5;
    int lane  = threadIdx.x & 31;
    if (gwarp >= N) return;
    float nx = normals[gwarp * 3 + 0];
    float ny = normals[gwarp * 3 + 1];
    float nz = normals[gwarp * 3 + 2];
    const float* ldp = ldir + (size_t)gwarp * L * 3;
    const float* lcp = lcol + (size_t)gwarp * L * 3;
    const float* vp  = vis  + (size_t)gwarp * L;
    float s0 = 0.f, s1 = 0.f, s2 = 0.f;
    int cnt = 0;
    for (int j = lane; j < L; j += 32) {
        float dx = ldp[j * 3 + 0], dy = ldp[j * 3 + 1], dz = ldp[j * 3 + 2];
        float d  = fmaf(nx, dx, fmaf(ny, dy, nz * dz));
        cnt += (d > 0.f) ? 1 : 0;
        d = fminf(fmaxf(d, 0.f), 1.f);
        float dv = d * vp[j];
        s0 = fmaf(dv, lcp[j * 3 + 0], s0);
        s1 = fmaf(dv, lcp[j * 3 + 1], s1);
        s2 = fmaf(dv, lcp[j * 3 + 2], s2);
    }
    #pragma unroll
    for (int off = 16; off; off >>= 1) {
        s0  += __shfl_xor_sync(0xFFFFFFFFu, s0,  off);
        s1  += __shfl_xor_sync(0xFFFFFFFFu, s1,  off);
        s2  += __shfl_xor_sync(0xFFFFFFFFu, s2,  off);
        cnt += __shfl_xor_sync(0xFFFFFFFFu, cnt, off);
    }
    if (lane == 0) {
        float c   = (cnt > 0) ? (float)cnt : 1.0f;
        float inv = 1.0f / c;
        float w   = weights[gwarp];
        int r;
        if (g_idx_is64) r = (int)((const long long*)ray_idx)[gwarp];
        else            r = ((const int*)ray_idx)[gwarp];
        atomicAdd(&g_acc[r * 4 + 0], w * albedos[gwarp * 3 + 0] * s0 * inv);
        atomicAdd(&g_acc[r * 4 + 1], w * albedos[gwarp * 3 + 1] * s1 * inv);
        atomicAdd(&g_acc[r * 4 + 2], w * albedos[gwarp * 3 + 2] * s2 * inv);
        atomicAdd(&g_acc[r * 4 + 3], w);
    }
}

extern "C" void kernel_launch(void* const* d_in, const int* in_sizes, int n_in,
                              void* d_out, int out_size) {
    const float* albedos = (const float*)d_in[0];
    const float* normals = (const float*)d_in[1];
    const float* ldir    = (const float*)d_in[2];
    const float* lcol    = (const float*)d_in[3];
    const float* vis     = (const float*)d_in[4];
    const float* bg      = (const float*)d_in[5];
    const float* weights = (const float*)d_in[6];
    const void*  ray_idx = (const void*) d_in[7];
    float* out = (float*)d_out;

    int N = in_sizes[0] / 3;
    int L = (N > 0) ? in_sizes[2] / (N * 3) : 1;
    int R = out_size / 3;
    if (R > MAX_RAYS) R = MAX_RAYS;

    detect_idx_kernel<<<1, 1024>>>((const int*)ray_idx, in_sizes[7]);

    int n4 = R * 4;
    zero_acc_kernel<<<(n4 + 255) / 256, 256>>>(n4);

    if (L == 64) {
        static int smem_set = 0;
        if (!smem_set) {
            cudaFuncSetAttribute(shade_pipe_kernel,
                                 cudaFuncAttributeMaxDynamicSharedMemorySize,
                                 SMEM_BYTES);
            smem_set = 1;
        }
        int ntiles = (N + SPB - 1) / SPB;
        int grid = 296;                 // 2 CTAs per SM (84KB smem each)
        if (grid > ntiles) grid = ntiles;
        shade_pipe_kernel<<<grid, 256, SMEM_BYTES>>>(
            albedos, normals, ldir, lcol, vis, weights, ray_idx, N, ntiles);
    } else {
        int blocks = (N + 7) / 8;
        shade_kernel_generic<<<blocks, 256>>>(
            albedos, normals, ldir, lcol, vis, weights, ray_idx, N, L);
    }

    finalize_kernel<<<(R + 255) / 256, 256>>>(bg, out, R);
}